// round 1
// baseline (speedup 1.0000x reference)
#include <cuda_runtime.h>
#include <cuda_bf16.h>
#include <math.h>

// Problem constants
#define BB 2
#define LL 192
#define HH 512
#define NHH 8
#define DPHH 64
#define MAXLEN 512
#define NDELTA 383   // deltas -191..191
#define BL (BB*LL)   // 384

// ---------------- device scratch (no allocation allowed) ----------------
__device__ float g_q [BL*HH];
__device__ float g_k [BL*HH];
__device__ float g_v [BL*HH];
__device__ float g_qv[BL*HH];
__device__ float g_gt[4*NDELTA*HH];   // 4 tables [383][512], b_fus baked into table 0
__device__ float g_wt[BL*NHH*HH];     // W~ [bq][n][f]
__device__ float g_cd[BL*NHH];        // constD
__device__ float g_x [BL*HH];         // pre-FF output

// ---------------- generic batched strided SGEMM ----------------
// C[m,n] = sum_k A[m*a_sm + k*a_sk] * B[n*b_sn + k*b_sk] + bias[n]
// Tile: 32 rows x 64 cols, 256 threads, 2x4 micro-tile.
struct Batch8 {
    const float* A[8];
    const float* B[8];
    const float* bias[8];
    float*       C[8];
};

__device__ __forceinline__ float dot4(float4 a, float4 b) {
    return a.x*b.x + a.y*b.y + a.z*b.z + a.w*b.w;
}

__global__ void __launch_bounds__(256) sgemm_b(
    Batch8 gb, int a_sm, int a_sk, int b_sn, int b_sk, int c_sm,
    int M, int N, int K)
{
    const float* A    = gb.A[blockIdx.z];
    const float* B    = gb.B[blockIdx.z];
    const float* bias = gb.bias[blockIdx.z];
    float*       C    = gb.C[blockIdx.z];

    __shared__ __align__(16) float As[16][36];
    __shared__ __align__(16) float Bs[16][68];

    const int t  = threadIdx.x;
    const int tx = t & 15, ty = t >> 4;
    const int row0 = blockIdx.y << 5;
    const int col0 = blockIdx.x << 6;

    float acc[2][4] = {{0.f,0.f,0.f,0.f},{0.f,0.f,0.f,0.f}};

    for (int k0 = 0; k0 < K; k0 += 16) {
        #pragma unroll
        for (int e = t; e < 512; e += 256) {
            int kk = e & 15, mm = e >> 4;
            int m = row0 + mm, kg = k0 + kk;
            As[kk][mm] = (m < M && kg < K)
                ? A[(size_t)m * a_sm + (size_t)kg * a_sk] : 0.f;
        }
        #pragma unroll
        for (int e = t; e < 1024; e += 256) {
            int kk = e & 15, nn = e >> 4;
            int n = col0 + nn, kg = k0 + kk;
            Bs[kk][nn] = (n < N && kg < K)
                ? B[(size_t)n * b_sn + (size_t)kg * b_sk] : 0.f;
        }
        __syncthreads();
        #pragma unroll
        for (int kk = 0; kk < 16; kk++) {
            float2 a2 = *(const float2*)&As[kk][ty << 1];
            float4 b4 = *(const float4*)&Bs[kk][tx << 2];
            acc[0][0] += a2.x * b4.x; acc[0][1] += a2.x * b4.y;
            acc[0][2] += a2.x * b4.z; acc[0][3] += a2.x * b4.w;
            acc[1][0] += a2.y * b4.x; acc[1][1] += a2.y * b4.y;
            acc[1][2] += a2.y * b4.z; acc[1][3] += a2.y * b4.w;
        }
        __syncthreads();
    }

    #pragma unroll
    for (int im = 0; im < 2; im++) {
        int m = row0 + (ty << 1) + im;
        if (m >= M) continue;
        #pragma unroll
        for (int jn = 0; jn < 4; jn++) {
            int n = col0 + (tx << 2) + jn;
            if (n < N)
                C[(size_t)m * c_sm + n] = acc[im][jn] + (bias ? bias[n] : 0.f);
        }
    }
}

// ---------------- elementwise helpers ----------------
__global__ void qv_kernel(const float* __restrict__ q,
                          const float* __restrict__ vbias,
                          float* __restrict__ qv)
{
    int i = blockIdx.x * 512 + threadIdx.x;
    qv[i] = q[i] + vbias[threadIdx.x];
}

__global__ void constd_kernel(const float* __restrict__ qv,
                              const float* __restrict__ br,
                              float* __restrict__ cd)
{
    int m = blockIdx.x * 256 + threadIdx.x;   // 0..3071
    if (m < BL * NHH) {
        const float* a = qv + (size_t)m * 64;
        const float* b = br + (m & 7) * 64;
        float s = 0.f;
        #pragma unroll
        for (int d = 0; d < 64; d++) s += a[d] * b[d];
        cd[m] = s;
    }
}

// ---------------- fused attention kernel: one CTA per (b, q) ----------------
__global__ void __launch_bounds__(256) attn_kernel(
    const float* __restrict__ kbuf,
    const float* __restrict__ vbuf,
    const float* __restrict__ qbuf,
    const float* __restrict__ gtab,
    const float* __restrict__ wt,
    const float* __restrict__ cdg,
    const float* __restrict__ u_bias,
    const int*   __restrict__ pos_s,
    const int*   __restrict__ pos_e,
    const int*   __restrict__ seq_len,
    float* __restrict__ xbuf)
{
    const int BQ = blockIdx.x;            // 0..383
    const int b  = BQ / LL;
    const int qi = BQ - b * LL;

    __shared__ __align__(16) float wts[8][512];
    __shared__ __align__(16) float qus[512];
    __shared__ float sc[8][192];          // rel part, then attn weights
    __shared__ float sA[192][8];          // (A + C) part
    __shared__ int   ps[192], pev[192];
    __shared__ float cd[8];

    const int tid  = threadIdx.x;
    const int warp = tid >> 5;
    const int lane = tid & 31;

    for (int f = tid; f < 4096; f += 256)
        wts[f >> 9][f & 511] = wt[(size_t)BQ * 4096 + f];
    for (int f = tid; f < 512; f += 256)
        qus[f] = qbuf[(size_t)BQ * 512 + f] + u_bias[f];
    if (tid < 192) { ps[tid] = pos_s[b * LL + tid]; pev[tid] = pos_e[b * LL + tid]; }
    if (tid < 8)   cd[tid] = cdg[BQ * 8 + tid];
    __syncthreads();

    const int sq = ps[qi], eq = pev[qi];
    const int slen = seq_len[b];

    const float* g0 = gtab;
    const float* g1 = gtab + 1 * NDELTA * 512;
    const float* g2 = gtab + 2 * NDELTA * 512;
    const float* g3 = gtab + 3 * NDELTA * 512;
    const float* krow = kbuf + (size_t)b * LL * 512;

    // each warp handles 24 contiguous k, 4 at a time (register blocked)
    const int kbeg = warp * 24;
    for (int k0 = kbeg; k0 < kbeg + 24; k0 += 4) {
        int o0[4], o1[4], o2[4], o3[4];
        #pragma unroll
        for (int kk = 0; kk < 4; kk++) {
            int sk = ps[k0 + kk], ek = pev[k0 + kk];
            o0[kk] = (sq - sk + 191) << 9;
            o1[kk] = (sq - ek + 191) << 9;
            o2[kk] = (eq - sk + 191) << 9;
            o3[kk] = (eq - ek + 191) << 9;
        }
        float acc[4][8];
        float accA[4][4];
        #pragma unroll
        for (int kk = 0; kk < 4; kk++) {
            #pragma unroll
            for (int n = 0; n < 8; n++) acc[kk][n] = 0.f;
            #pragma unroll
            for (int i = 0; i < 4; i++) accA[kk][i] = 0.f;
        }

        #pragma unroll
        for (int i = 0; i < 4; i++) {
            const int f = (lane << 2) + (i << 7);
            float4 qu4 = *(const float4*)&qus[f];
            float4 z[4];
            #pragma unroll
            for (int kk = 0; kk < 4; kk++) {
                float4 a0 = *(const float4*)(g0 + o0[kk] + f);
                float4 a1 = *(const float4*)(g1 + o1[kk] + f);
                float4 a2 = *(const float4*)(g2 + o2[kk] + f);
                float4 a3 = *(const float4*)(g3 + o3[kk] + f);
                z[kk].x = fmaxf(a0.x + a1.x + a2.x + a3.x, 0.f);
                z[kk].y = fmaxf(a0.y + a1.y + a2.y + a3.y, 0.f);
                z[kk].z = fmaxf(a0.z + a1.z + a2.z + a3.z, 0.f);
                z[kk].w = fmaxf(a0.w + a1.w + a2.w + a3.w, 0.f);
                float4 kr = *(const float4*)(krow + (size_t)(k0 + kk) * 512 + f);
                accA[kk][i] += dot4(qu4, kr);
            }
            #pragma unroll
            for (int n = 0; n < 8; n++) {
                float4 w4 = *(const float4*)&wts[n][f];
                #pragma unroll
                for (int kk = 0; kk < 4; kk++)
                    acc[kk][n] += dot4(z[kk], w4);
            }
        }

        #pragma unroll
        for (int kk = 0; kk < 4; kk++) {
            #pragma unroll
            for (int n = 0; n < 8; n++) {
                float v = acc[kk][n];
                #pragma unroll
                for (int s = 16; s > 0; s >>= 1)
                    v += __shfl_xor_sync(0xffffffffu, v, s);
                acc[kk][n] = v;
            }
            #pragma unroll
            for (int i = 0; i < 4; i++) {
                float v = accA[kk][i];
                #pragma unroll
                for (int s = 8; s > 0; s >>= 1)
                    v += __shfl_xor_sync(0xffffffffu, v, s);
                accA[kk][i] = v;
            }
            if (lane == 0) {
                #pragma unroll
                for (int n = 0; n < 8; n++) sc[n][k0 + kk] = acc[kk][n];
            }
            if ((lane & 15) == 0) {
                int h = lane >> 4;
                #pragma unroll
                for (int i = 0; i < 4; i++)
                    sA[k0 + kk][2 * i + h] = accA[kk][i];
            }
        }
    }
    __syncthreads();

    // softmax: warp n handles head n over 192 keys (6 per lane)
    {
        float vals[6];
        float mx = -1e30f;
        #pragma unroll
        for (int j = 0; j < 6; j++) {
            int k = lane + (j << 5);
            float v = (sc[warp][k] + sA[k][warp] + cd[warp]) * 0.125f;
            v = (k < slen) ? v : -1e30f;
            vals[j] = v;
            mx = fmaxf(mx, v);
        }
        #pragma unroll
        for (int s = 16; s > 0; s >>= 1)
            mx = fmaxf(mx, __shfl_xor_sync(0xffffffffu, mx, s));
        float se = 0.f;
        float ev[6];
        #pragma unroll
        for (int j = 0; j < 6; j++) {
            ev[j] = (vals[j] > -1e29f) ? expf(vals[j] - mx) : 0.f;
            se += ev[j];
        }
        #pragma unroll
        for (int s = 16; s > 0; s >>= 1)
            se += __shfl_xor_sync(0xffffffffu, se, s);
        float inv = 1.f / se;
        #pragma unroll
        for (int j = 0; j < 6; j++)
            sc[warp][lane + (j << 5)] = ev[j] * inv;
    }
    __syncthreads();

    // output: thread handles 2 consecutive dims; head(f0)=tid>>5=warp
    {
        const float* vb = vbuf + (size_t)b * LL * 512;
        const int f0 = tid << 1;
        float ox = 0.f, oy = 0.f;
        for (int k = 0; k < 192; k++) {
            float a = sc[warp][k];
            float2 vv = *(const float2*)(vb + (size_t)k * 512 + f0);
            ox += a * vv.x;
            oy += a * vv.y;
        }
        float2 o2 = make_float2(ox, oy);
        *(float2*)(xbuf + (size_t)BQ * 512 + f0) = o2;
    }
}

// ---------------- launch ----------------
extern "C" void kernel_launch(void* const* d_in, const int* in_sizes, int n_in,
                              void* d_out, int out_size)
{
    // optional scalar lex_num at index 4
    int off = (n_in > 4 && in_sizes[4] == 1) ? 1 : 0;

    const float* key   = (const float*)d_in[0];
    const float* query = (const float*)d_in[1];
    const float* value = (const float*)d_in[2];
    const int*   seqlp = (const int*)  d_in[3];
    const int*   pos_s = (const int*)  d_in[4 + off];
    const int*   pos_e = (const int*)  d_in[5 + off];
    const float* pe    = (const float*)d_in[6 + off];
    const float* W_fus = (const float*)d_in[7 + off];
    const float* b_fus = (const float*)d_in[8 + off];
    const float* Wk    = (const float*)d_in[9 + off];
    const float* bk    = (const float*)d_in[10 + off];
    const float* Wq    = (const float*)d_in[11 + off];
    const float* bq    = (const float*)d_in[12 + off];
    const float* Wv    = (const float*)d_in[13 + off];
    const float* bv    = (const float*)d_in[14 + off];
    const float* Wr    = (const float*)d_in[15 + off];
    const float* br    = (const float*)d_in[16 + off];
    const float* ub    = (const float*)d_in[17 + off];
    const float* vb    = (const float*)d_in[18 + off];
    const float* Wff   = (const float*)d_in[19 + off];
    const float* bff   = (const float*)d_in[20 + off];
    float* out = (float*)d_out;

    float *p_q, *p_k, *p_v, *p_qv, *p_gt, *p_wt, *p_cd, *p_x;
    cudaGetSymbolAddress((void**)&p_q,  g_q);
    cudaGetSymbolAddress((void**)&p_k,  g_k);
    cudaGetSymbolAddress((void**)&p_v,  g_v);
    cudaGetSymbolAddress((void**)&p_qv, g_qv);
    cudaGetSymbolAddress((void**)&p_gt, g_gt);
    cudaGetSymbolAddress((void**)&p_wt, g_wt);
    cudaGetSymbolAddress((void**)&p_cd, g_cd);
    cudaGetSymbolAddress((void**)&p_x,  g_x);

    // 1) q/k/v projections: [384,512] @ [512,512]^T + bias
    {
        Batch8 gb = {};
        gb.A[0] = query; gb.B[0] = Wq; gb.bias[0] = bq; gb.C[0] = p_q;
        gb.A[1] = key;   gb.B[1] = Wk; gb.bias[1] = bk; gb.C[1] = p_k;
        gb.A[2] = value; gb.B[2] = Wv; gb.bias[2] = bv; gb.C[2] = p_v;
        sgemm_b<<<dim3(8, 12, 3), 256>>>(gb, 512, 1, 512, 1, 512, BL, 512, 512);
    }

    // 2) delta tables: g_t[di][f] = pe[di+321, :256] . W_fus[f, t*256 : t*256+256]
    {
        Batch8 gb = {};
        for (int t = 0; t < 4; t++) {
            gb.A[t]    = pe + 321 * 512;
            gb.B[t]    = W_fus + t * 256;
            gb.bias[t] = (t == 0) ? b_fus : nullptr;
            gb.C[t]    = p_gt + (size_t)t * NDELTA * 512;
        }
        sgemm_b<<<dim3(8, 12, 4), 256>>>(gb, 512, 1, 1024, 1, 512, NDELTA, 512, 256);
    }

    // 3) qv = q + v_bias ; constD
    qv_kernel<<<BL, 512>>>(p_q, vb, p_qv);
    constd_kernel<<<12, 256>>>(p_qv, br, p_cd);

    // 4) W~[bq,n,f] = sum_d qv[bq, n*64+d] * Wr[n*64+d, f]
    {
        Batch8 gb = {};
        for (int nh = 0; nh < 8; nh++) {
            gb.A[nh]    = p_qv + nh * 64;
            gb.B[nh]    = Wr + (size_t)nh * 64 * 512;
            gb.bias[nh] = nullptr;
            gb.C[nh]    = p_wt + nh * 512;
        }
        sgemm_b<<<dim3(8, 12, 8), 256>>>(gb, 512, 1, 1, 512, 4096, BL, 512, 64);
    }

    // 5) fused attention
    attn_kernel<<<BL, 256>>>(p_k, p_v, p_q, p_gt, p_wt, p_cd, ub,
                             pos_s, pos_e, seqlp, p_x);

    // 6) final: out = X @ Wff^T + bff
    {
        Batch8 gb = {};
        gb.A[0] = p_x; gb.B[0] = Wff; gb.bias[0] = bff; gb.C[0] = out;
        sgemm_b<<<dim3(8, 12, 1), 256>>>(gb, 512, 1, 512, 1, 512, BL, 512, 512);
    }
}